// round 8
// baseline (speedup 1.0000x reference)
#include <cuda_runtime.h>
#include <cuda_bf16.h>
#include <cstdint>

// Problem (fixed shapes): N_NODES=50000, N_EDGES=800000, D_FEAT=64
//   out = segment_sum(x[src] * e, dst, N_NODES)
//
// Strategy: fixed-capacity per-dst buckets (atomic cursor) + atomic-free
// warp-per-node gather. dst ~ Poisson(16); P(degree >= 96) ~ e^-92 ->
// CAP=96 unreachable (guarded for safety).
//
// Gather hot loop: records fetched COALESCED (one LDG.64 per lane per 32
// edges), staged in shared memory, then read back with uniform-address
// LDS.128 (broadcast, conflict-free). No SHFL, no dependent global record
// chain. ~4.5 instructions per edge; x-row loads have MLP=4.

#define N_NODES 50000
#define D_FEAT  64
#define CAP     96          // bucket row: 96*8B = 768B (16B-aligned stride)
#define WARPS_PER_BLOCK 8

__device__ int  g_cnt[N_NODES];
__device__ int2 g_bucket[(size_t)N_NODES * CAP];   // (src*32, bits(w))

// ------------------------------------------------------------ K1: scatter
// 8 edges per thread -> 8 independent atomic->store chains (MLP=8).
__global__ void bucket_scatter_kernel(const float* __restrict__ e,
                                      const int*   __restrict__ src,
                                      const int*   __restrict__ dst,
                                      int n_edges) {
    int i0 = (blockIdx.x * blockDim.x + threadIdx.x) * 8;
    if (i0 + 7 < n_edges) {
        int4   da = *reinterpret_cast<const int4*>(dst + i0);
        int4   db = *reinterpret_cast<const int4*>(dst + i0 + 4);
        int4   sa = *reinterpret_cast<const int4*>(src + i0);
        int4   sb = *reinterpret_cast<const int4*>(src + i0 + 4);
        float4 ea = *reinterpret_cast<const float4*>(e + i0);
        float4 eb = *reinterpret_cast<const float4*>(e + i0 + 4);
        int   d[8] = {da.x, da.y, da.z, da.w, db.x, db.y, db.z, db.w};
        int   s[8] = {sa.x, sa.y, sa.z, sa.w, sb.x, sb.y, sb.z, sb.w};
        float w[8] = {ea.x, ea.y, ea.z, ea.w, eb.x, eb.y, eb.z, eb.w};
#pragma unroll
        for (int q = 0; q < 8; q++) {
            int pos = atomicAdd(&g_cnt[d[q]], 1);
            if (pos < CAP)
                g_bucket[(size_t)d[q] * CAP + pos] =
                    make_int2(s[q] * (D_FEAT / 2), __float_as_int(w[q]));
        }
    } else {
        for (int i = i0; i < n_edges; i++) {
            int dd  = dst[i];
            int pos = atomicAdd(&g_cnt[dd], 1);
            if (pos < CAP)
                g_bucket[(size_t)dd * CAP + pos] =
                    make_int2(src[i] * (D_FEAT / 2), __float_as_int(e[i]));
        }
    }
}

// ------------------------------------------------------------- K2: gather
// One warp per node; lane owns a float2 column of the 64-float row.
__global__ void __launch_bounds__(WARPS_PER_BLOCK * 32)
gather_kernel(const float* __restrict__ x,
              float* __restrict__ out,
              int n_nodes) {
    __shared__ int2 s_rec[WARPS_PER_BLOCK][32];

    int w    = threadIdx.x >> 5;
    int lane = threadIdx.x & 31;
    int node = blockIdx.x * WARPS_PER_BLOCK + w;
    if (node >= n_nodes) return;

    int cnt = g_cnt[node];
    if (cnt > CAP) cnt = CAP;          // unreachable in practice

    const int2*   __restrict__ brow = g_bucket + (size_t)node * CAP;
    const float2* __restrict__ xp   = reinterpret_cast<const float2*>(x);

    float accx = 0.f, accy = 0.f;

    for (int base = 0; base < cnt; base += 32) {
        int m = cnt - base; if (m > 32) m = 32;
        // coalesced record fetch for up to 32 edges, staged in smem
        if (lane < m) s_rec[w][lane] = __ldg(&brow[base + lane]);
        __syncwarp();

        const int4* __restrict__ sr4 = reinterpret_cast<const int4*>(s_rec[w]);
        int k = 0;
        for (; k + 4 <= m; k += 4) {
            int4 ra = sr4[(k >> 1) + 0];   // records k, k+1  (uniform LDS.128)
            int4 rb = sr4[(k >> 1) + 1];   // records k+2, k+3

            float2 v0 = __ldg(&xp[ra.x + lane]);
            float2 v1 = __ldg(&xp[ra.z + lane]);
            float2 v2 = __ldg(&xp[rb.x + lane]);
            float2 v3 = __ldg(&xp[rb.z + lane]);

            accx = fmaf(v0.x, __int_as_float(ra.y), accx);
            accy = fmaf(v0.y, __int_as_float(ra.y), accy);
            accx = fmaf(v1.x, __int_as_float(ra.w), accx);
            accy = fmaf(v1.y, __int_as_float(ra.w), accy);
            accx = fmaf(v2.x, __int_as_float(rb.y), accx);
            accy = fmaf(v2.y, __int_as_float(rb.y), accy);
            accx = fmaf(v3.x, __int_as_float(rb.w), accx);
            accy = fmaf(v3.y, __int_as_float(rb.w), accy);
        }
        for (; k < m; k++) {               // 0-3 tail edges
            int2   r = s_rec[w][k];
            float2 v = __ldg(&xp[r.x + lane]);
            accx = fmaf(v.x, __int_as_float(r.y), accx);
            accy = fmaf(v.y, __int_as_float(r.y), accy);
        }
        __syncwarp();
    }

    float2 res; res.x = accx; res.y = accy;
    reinterpret_cast<float2*>(out)[(size_t)node * (D_FEAT / 2) + lane] = res;
}

extern "C" void kernel_launch(void* const* d_in, const int* in_sizes, int n_in,
                              void* d_out, int out_size) {
    // Identify inputs by element count:
    //   x : 3,200,000 floats; e, src, dst : 800,000 each in metadata order.
    const float* x   = nullptr;
    const float* e   = nullptr;
    const int*   src = nullptr;
    const int*   dst = nullptr;
    int n_edges = 0;

    int big_seen = 0;
    for (int i = 0; i < n_in; i++) {
        int sz = in_sizes[i];
        if (sz >= 1000000) {
            x = (const float*)d_in[i];
        } else if (sz >= 100000) {
            n_edges = sz;
            if (big_seen == 0)      e   = (const float*)d_in[i];
            else if (big_seen == 1) src = (const int*)d_in[i];
            else                    dst = (const int*)d_in[i];
            big_seen++;
        }
    }

    int n_nodes = out_size / D_FEAT;   // 50000

    // Zero the per-node counters (200 KB).
    void* cnt_ptr = nullptr;
    cudaGetSymbolAddress(&cnt_ptr, g_cnt);
    cudaMemsetAsync(cnt_ptr, 0, N_NODES * sizeof(int));

    const int B = 256;
    int scat_threads = (n_edges + 7) / 8;
    bucket_scatter_kernel<<<(scat_threads + B - 1) / B, B>>>(e, src, dst, n_edges);

    int blocks = (n_nodes + WARPS_PER_BLOCK - 1) / WARPS_PER_BLOCK;
    gather_kernel<<<blocks, WARPS_PER_BLOCK * 32>>>(x, (float*)d_out, n_nodes);
}

// round 9
// speedup vs baseline: 1.4068x; 1.4068x over previous
#include <cuda_runtime.h>
#include <cuda_bf16.h>
#include <cstdint>

// Problem (fixed shapes): N_NODES=50000, N_EDGES=800000, D_FEAT=64
//   out = segment_sum(x[src] * e, dst, N_NODES)
//
// Strategy (R5 structure, proven fastest):
//   K1: fixed-capacity per-dst buckets (atomic cursor), records hold
//       (src*32, bits(w)) so gather addressing is add-only.
//   K2: warp-per-node gather. Records for 32 edges fetched with ONE
//       coalesced lane-parallel load, then broadcast via register SHFL
//       (no memory op in the broadcast path). 8 independent x-row loads
//       in flight per iteration. No atomics in the hot pass.
//   g_cnt starts zeroed (BSS) and is reset by K2 after use -> no memset
//   launch needed; graph replays stay consistent.

#define N_NODES 50000
#define D_FEAT  64
#define CAP     96          // Poisson(16): P(deg>=96) ~ e^-92, guarded anyway

__device__ int  g_cnt[N_NODES];                    // zero-init, self-resetting
__device__ int2 g_bucket[(size_t)N_NODES * CAP];   // (src*32, bits(w))

// ------------------------------------------------------------ K1: scatter
__global__ void bucket_scatter_kernel(const float* __restrict__ e,
                                      const int*   __restrict__ src,
                                      const int*   __restrict__ dst,
                                      int n_edges) {
    int i0 = (blockIdx.x * blockDim.x + threadIdx.x) * 8;
    if (i0 + 7 < n_edges) {
        int4   da = *reinterpret_cast<const int4*>(dst + i0);
        int4   db = *reinterpret_cast<const int4*>(dst + i0 + 4);
        int4   sa = *reinterpret_cast<const int4*>(src + i0);
        int4   sb = *reinterpret_cast<const int4*>(src + i0 + 4);
        float4 ea = *reinterpret_cast<const float4*>(e + i0);
        float4 eb = *reinterpret_cast<const float4*>(e + i0 + 4);
        int   d[8] = {da.x, da.y, da.z, da.w, db.x, db.y, db.z, db.w};
        int   s[8] = {sa.x, sa.y, sa.z, sa.w, sb.x, sb.y, sb.z, sb.w};
        float w[8] = {ea.x, ea.y, ea.z, ea.w, eb.x, eb.y, eb.z, eb.w};
#pragma unroll
        for (int q = 0; q < 8; q++) {
            int pos = atomicAdd(&g_cnt[d[q]], 1);
            if (pos < CAP)
                g_bucket[(size_t)d[q] * CAP + pos] =
                    make_int2(s[q] * (D_FEAT / 2), __float_as_int(w[q]));
        }
    } else {
        for (int i = i0; i < n_edges; i++) {
            int dd  = dst[i];
            int pos = atomicAdd(&g_cnt[dd], 1);
            if (pos < CAP)
                g_bucket[(size_t)dd * CAP + pos] =
                    make_int2(src[i] * (D_FEAT / 2), __float_as_int(e[i]));
        }
    }
}

// ------------------------------------------------------------- K2: gather
// One warp per node; lane owns a float2 column. 8 edges per inner step.
__global__ void gather_kernel(const float* __restrict__ x,
                              float* __restrict__ out,
                              int n_nodes) {
    int node = (blockIdx.x * blockDim.x + threadIdx.x) >> 5;
    int lane = threadIdx.x & 31;
    if (node >= n_nodes) return;

    int cnt = g_cnt[node];
    if (cnt > CAP) cnt = CAP;          // unreachable in practice

    const int2*   __restrict__ brow = g_bucket + (size_t)node * CAP;
    const float2* __restrict__ xl   = reinterpret_cast<const float2*>(x) + lane;

    float accx = 0.f, accy = 0.f;

    for (int base = 0; base < cnt; base += 32) {
        int idx = base + lane;
        // one coalesced record fetch per 32 edges; pad lanes are exact no-ops
        int2 rec = (idx < cnt) ? __ldg(&brow[idx]) : make_int2(0, 0);
        int m  = cnt - base; if (m > 32) m = 32;
        int mm = (m + 7) & ~7;          // pad to multiple of 8 (w=0 padding)

        for (int k = 0; k < mm; k += 8) {
            int s0 = __shfl_sync(0xffffffffu, rec.x, k + 0);
            int s1 = __shfl_sync(0xffffffffu, rec.x, k + 1);
            int s2 = __shfl_sync(0xffffffffu, rec.x, k + 2);
            int s3 = __shfl_sync(0xffffffffu, rec.x, k + 3);
            int s4 = __shfl_sync(0xffffffffu, rec.x, k + 4);
            int s5 = __shfl_sync(0xffffffffu, rec.x, k + 5);
            int s6 = __shfl_sync(0xffffffffu, rec.x, k + 6);
            int s7 = __shfl_sync(0xffffffffu, rec.x, k + 7);

            // 8 independent gathers in flight (src pre-multiplied by 32)
            float2 v0 = __ldg(xl + s0);
            float2 v1 = __ldg(xl + s1);
            float2 v2 = __ldg(xl + s2);
            float2 v3 = __ldg(xl + s3);
            float2 v4 = __ldg(xl + s4);
            float2 v5 = __ldg(xl + s5);
            float2 v6 = __ldg(xl + s6);
            float2 v7 = __ldg(xl + s7);

            float w0 = __int_as_float(__shfl_sync(0xffffffffu, rec.y, k + 0));
            float w1 = __int_as_float(__shfl_sync(0xffffffffu, rec.y, k + 1));
            float w2 = __int_as_float(__shfl_sync(0xffffffffu, rec.y, k + 2));
            float w3 = __int_as_float(__shfl_sync(0xffffffffu, rec.y, k + 3));
            float w4 = __int_as_float(__shfl_sync(0xffffffffu, rec.y, k + 4));
            float w5 = __int_as_float(__shfl_sync(0xffffffffu, rec.y, k + 5));
            float w6 = __int_as_float(__shfl_sync(0xffffffffu, rec.y, k + 6));
            float w7 = __int_as_float(__shfl_sync(0xffffffffu, rec.y, k + 7));

            accx = fmaf(v0.x, w0, accx);  accy = fmaf(v0.y, w0, accy);
            accx = fmaf(v1.x, w1, accx);  accy = fmaf(v1.y, w1, accy);
            accx = fmaf(v2.x, w2, accx);  accy = fmaf(v2.y, w2, accy);
            accx = fmaf(v3.x, w3, accx);  accy = fmaf(v3.y, w3, accy);
            accx = fmaf(v4.x, w4, accx);  accy = fmaf(v4.y, w4, accy);
            accx = fmaf(v5.x, w5, accx);  accy = fmaf(v5.y, w5, accy);
            accx = fmaf(v6.x, w6, accx);  accy = fmaf(v6.y, w6, accy);
            accx = fmaf(v7.x, w7, accx);  accy = fmaf(v7.y, w7, accy);
        }
    }

    // self-reset counter for the next graph replay (read happened above)
    if (lane == 0) g_cnt[node] = 0;

    float2 res; res.x = accx; res.y = accy;
    reinterpret_cast<float2*>(out)[(size_t)node * (D_FEAT / 2) + lane] = res;
}

extern "C" void kernel_launch(void* const* d_in, const int* in_sizes, int n_in,
                              void* d_out, int out_size) {
    // Identify inputs by element count:
    //   x : 3,200,000 floats; e, src, dst : 800,000 each in metadata order.
    const float* x   = nullptr;
    const float* e   = nullptr;
    const int*   src = nullptr;
    const int*   dst = nullptr;
    int n_edges = 0;

    int big_seen = 0;
    for (int i = 0; i < n_in; i++) {
        int sz = in_sizes[i];
        if (sz >= 1000000) {
            x = (const float*)d_in[i];
        } else if (sz >= 100000) {
            n_edges = sz;
            if (big_seen == 0)      e   = (const float*)d_in[i];
            else if (big_seen == 1) src = (const int*)d_in[i];
            else                    dst = (const int*)d_in[i];
            big_seen++;
        }
    }

    int n_nodes = out_size / D_FEAT;   // 50000

    const int B = 256;
    int scat_threads = (n_edges + 7) / 8;
    bucket_scatter_kernel<<<(scat_threads + B - 1) / B, B>>>(e, src, dst, n_edges);

    int total = n_nodes * 32;          // one warp per node
    gather_kernel<<<(total + B - 1) / B, B>>>(x, (float*)d_out, n_nodes);
}